// round 1
// baseline (speedup 1.0000x reference)
#include <cuda_runtime.h>
#include <math.h>

#define BB   64
#define NN   256
#define HIDD 256
#define HH   4
#define CC   64
#define EE   8192
#define FIN  768
#define PAD  68

// ---------------- scratch (no allocations allowed) ----------------
__device__ float g_H [(size_t)BB * NN * HIDD];
__device__ float g_H2[(size_t)BB * NN * HIDD];
__device__ float g_XL[(size_t)BB * NN * HIDD];
__device__ float g_XR[(size_t)BB * NN * HIDD];
__device__ float g_pool[BB * HIDD];
__device__ int   g_srcs[EE];
__device__ int   g_dsts[EE];
__device__ int   g_off[NN + 1];

__device__ __forceinline__ float gelu_f(float x) {
    return 0.5f * x * (1.0f + erff(x * 0.70710678118654752f));
}

// ---------------- deterministic stable counting sort of edges by dst ----------------
__global__ void sort_edges_kernel(const int* __restrict__ src, const int* __restrict__ dst) {
    __shared__ int sd[EE];        // 32 KB
    __shared__ int cnt[NN + 1];
    int tid = threadIdx.x;        // 256 threads, thread t owns dst value t
    for (int e = tid; e < EE; e += 256) sd[e] = dst[e];
    if (tid == 0) cnt[0] = 0;
    __syncthreads();
    int c = 0;
    #pragma unroll 4
    for (int e = 0; e < EE; e++) if (sd[e] == tid) c++;
    cnt[tid + 1] = c;
    __syncthreads();
    if (tid == 0) {
        for (int i = 1; i <= NN; i++) cnt[i] += cnt[i - 1];
    }
    __syncthreads();
    int pos = cnt[tid];
    #pragma unroll 4
    for (int e = 0; e < EE; e++) {
        if (sd[e] == tid) {
            g_srcs[pos] = src[e];
            g_dsts[pos] = tid;
            pos++;
        }
    }
    g_off[tid + 1] = cnt[tid + 1];
    if (tid == 0) g_off[0] = 0;
}

// ---------------- generic tiled fp32 GEMM: C = A(MxK) * B(KxN) + epilogue ----------------
// MODE 0: out = acc + bias
// MODE 1: out = gelu(bn(acc + bias))   (BatchNorm eval with g/be/m/v)
template <int MODE>
__global__ void __launch_bounds__(256, 2)
gemm_kernel(const float* __restrict__ A, const float* __restrict__ B,
            const float* __restrict__ bias,
            const float* __restrict__ gam, const float* __restrict__ bet,
            const float* __restrict__ rm, const float* __restrict__ rv,
            float* __restrict__ C, int M, int Nn, int K) {
    const int BM = 128, BN = 64, BK = 16;
    __shared__ float As[BK][BM];
    __shared__ float Bs[BK][BN];
    int bm = blockIdx.x * BM;
    int bn = blockIdx.y * BN;
    int tid = threadIdx.x;
    int tx = tid & 15;   // N direction (x4)
    int ty = tid >> 4;   // M direction (x8)

    float acc[8][4];
    #pragma unroll
    for (int i = 0; i < 8; i++)
        #pragma unroll
        for (int j = 0; j < 4; j++) acc[i][j] = 0.f;

    for (int k0 = 0; k0 < K; k0 += BK) {
        // load A tile 128x16 as 512 float4, 2 per thread, store transposed
        #pragma unroll
        for (int i = 0; i < 2; i++) {
            int id = tid + i * 256;
            int r = id >> 2;
            int c4 = (id & 3) << 2;
            float4 va = *(const float4*)(A + (size_t)(bm + r) * K + k0 + c4);
            As[c4 + 0][r] = va.x;
            As[c4 + 1][r] = va.y;
            As[c4 + 2][r] = va.z;
            As[c4 + 3][r] = va.w;
        }
        // load B tile 16x64 = 256 float4, 1 per thread
        {
            int r = tid >> 4;
            int c4 = (tid & 15) << 2;
            *(float4*)&Bs[r][c4] = *(const float4*)(B + (size_t)(k0 + r) * Nn + bn + c4);
        }
        __syncthreads();
        #pragma unroll
        for (int kk = 0; kk < BK; kk++) {
            float4 ra0 = *(const float4*)&As[kk][ty * 8 + 0];
            float4 ra1 = *(const float4*)&As[kk][ty * 8 + 4];
            float4 rb  = *(const float4*)&Bs[kk][tx * 4];
            float ra[8] = {ra0.x, ra0.y, ra0.z, ra0.w, ra1.x, ra1.y, ra1.z, ra1.w};
            float rbv[4] = {rb.x, rb.y, rb.z, rb.w};
            #pragma unroll
            for (int i = 0; i < 8; i++)
                #pragma unroll
                for (int j = 0; j < 4; j++)
                    acc[i][j] = fmaf(ra[i], rbv[j], acc[i][j]);
        }
        __syncthreads();
    }

    // epilogue
    int col0 = bn + tx * 4;
    float bia[4], ga[4], be_[4], mm[4], vv[4];
    #pragma unroll
    for (int j = 0; j < 4; j++) bia[j] = bias[col0 + j];
    if (MODE == 1) {
        #pragma unroll
        for (int j = 0; j < 4; j++) {
            ga[j] = gam[col0 + j];
            be_[j] = bet[col0 + j];
            mm[j] = rm[col0 + j];
            vv[j] = rsqrtf(rv[col0 + j] + 1e-5f);
        }
    }
    #pragma unroll
    for (int i = 0; i < 8; i++) {
        int row = bm + ty * 8 + i;
        float4 o;
        float t[4];
        #pragma unroll
        for (int j = 0; j < 4; j++) {
            t[j] = acc[i][j] + bia[j];
            if (MODE == 1) {
                t[j] = (t[j] - mm[j]) * vv[j] * ga[j] + be_[j];
                t[j] = gelu_f(t[j]);
            }
        }
        o.x = t[0]; o.y = t[1]; o.z = t[2]; o.w = t[3];
        *(float4*)(C + (size_t)row * Nn + col0) = o;
    }
}

// ---------------- GATv2 edge softmax + aggregation, one block per (sample, head) ----------------
__global__ void __launch_bounds__(256, 1)
gat_kernel(const float* __restrict__ XL, const float* __restrict__ XR,
           const float* __restrict__ att, const float* __restrict__ bo,
           float* __restrict__ OUT) {
    extern __shared__ float sm[];
    float* sxl  = sm;                    // NN*PAD
    float* sxr  = sxl + NN * PAD;        // NN*PAD
    float* slog = sxr + NN * PAD;        // EE
    float* smx  = slog + EE;             // NN
    float* sden = smx + NN;              // NN
    float* satt = sden + NN;             // CC

    int b = blockIdx.x, h = blockIdx.y;
    int tid = threadIdx.x;

    if (tid < CC) satt[tid] = att[h * CC + tid];
    const float* xlb = XL + (size_t)b * NN * HIDD + h * CC;
    const float* xrb = XR + (size_t)b * NN * HIDD + h * CC;
    for (int i = tid; i < NN * CC; i += 256) {
        int n = i >> 6, c = i & 63;
        sxl[n * PAD + c] = xlb[(size_t)n * HIDD + c];
        sxr[n * PAD + c] = xrb[(size_t)n * HIDD + c];
    }
    if (tid < NN) {
        smx[tid] = __int_as_float(0xff800000);  // -inf
        sden[tid] = 0.f;
    }
    __syncthreads();

    // pass 1: per-edge logits + smem float max
    for (int e = tid; e < EE; e += 256) {
        int s = g_srcs[e], d = g_dsts[e];
        const float* a = sxl + s * PAD;
        const float* r = sxr + d * PAD;
        float acc = 0.f;
        #pragma unroll
        for (int c = 0; c < CC; c += 4) {
            float4 va = *(const float4*)(a + c);
            float4 vr = *(const float4*)(r + c);
            float t;
            t = va.x + vr.x; t = t > 0.f ? t : 0.2f * t; acc = fmaf(satt[c + 0], t, acc);
            t = va.y + vr.y; t = t > 0.f ? t : 0.2f * t; acc = fmaf(satt[c + 1], t, acc);
            t = va.z + vr.z; t = t > 0.f ? t : 0.2f * t; acc = fmaf(satt[c + 2], t, acc);
            t = va.w + vr.w; t = t > 0.f ? t : 0.2f * t; acc = fmaf(satt[c + 3], t, acc);
        }
        slog[e] = acc;
        // atomic float max via CAS (smem)
        int* addr = (int*)&smx[d];
        int old = *addr;
        while (__int_as_float(old) < acc) {
            int assumed = old;
            old = atomicCAS(addr, assumed, __float_as_int(acc));
            if (old == assumed) break;
        }
    }
    __syncthreads();

    // pass 2: exp + denominator
    for (int e = tid; e < EE; e += 256) {
        int d = g_dsts[e];
        float a = expf(slog[e] - smx[d]);
        slog[e] = a;
        atomicAdd(&sden[d], a);
    }
    __syncthreads();

    // pass 3: warp per node, lane covers 2 channels
    int wid = tid >> 5, lane = tid & 31;
    int c0 = lane * 2;
    for (int n = wid; n < NN; n += 8) {
        int e0 = g_off[n], e1 = g_off[n + 1];
        float inv = 1.f / (sden[n] + 1e-16f);
        float a0 = 0.f, a1 = 0.f;
        for (int e = e0; e < e1; e++) {
            int s = g_srcs[e];
            float w = slog[e] * inv;
            float2 v = *(const float2*)(sxl + s * PAD + c0);
            a0 = fmaf(w, v.x, a0);
            a1 = fmaf(w, v.y, a1);
        }
        size_t o = ((size_t)b * NN + n) * HIDD + h * CC + c0;
        float t0 = a0 + bo[h * CC + c0];
        float t1 = a1 + bo[h * CC + c0 + 1];
        OUT[o]     = gelu_f(t0);
        OUT[o + 1] = gelu_f(t1);
    }
}

// ---------------- mean-pool over nodes ----------------
__global__ void pool_kernel(const float* __restrict__ H, float* __restrict__ P) {
    int b = blockIdx.x, f = threadIdx.x;
    float s = 0.f;
    #pragma unroll 4
    for (int n = 0; n < NN; n++) s += H[((size_t)b * NN + n) * HIDD + f];
    P[b * HIDD + f] = s * (1.0f / NN);
}

// ---------------- tiny output GEMM + BN + GELU ----------------
__global__ void gemm2_kernel(const float* __restrict__ P, const float* __restrict__ W,
                             const float* __restrict__ bias,
                             const float* __restrict__ gam, const float* __restrict__ bet,
                             const float* __restrict__ rm, const float* __restrict__ rv,
                             float* __restrict__ out) {
    __shared__ float sp[HIDD];
    int b = blockIdx.x, j = threadIdx.x;
    sp[j] = P[b * HIDD + j];
    __syncthreads();
    float acc = 0.f;
    #pragma unroll 4
    for (int k = 0; k < HIDD; k++) acc = fmaf(sp[k], W[(size_t)k * HIDD + j], acc);
    float t = acc + bias[j];
    t = (t - rm[j]) * rsqrtf(rv[j] + 1e-5f) * gam[j] + bet[j];
    out[b * HIDD + j] = gelu_f(t);
}

#define GAT_SMEM ((2 * NN * PAD + EE + 2 * NN + CC) * (int)sizeof(float))

extern "C" void kernel_launch(void* const* d_in, const int* in_sizes, int n_in,
                              void* d_out, int out_size) {
    const float* x    = (const float*)d_in[0];
    const int*   ei   = (const int*)d_in[1];
    const float* W1   = (const float*)d_in[2];
    const float* b1   = (const float*)d_in[3];
    const float* g1   = (const float*)d_in[4];
    const float* be1  = (const float*)d_in[5];
    const float* m1   = (const float*)d_in[6];
    const float* v1   = (const float*)d_in[7];
    const float* Wl0  = (const float*)d_in[8];
    const float* bl0  = (const float*)d_in[9];
    const float* Wr0  = (const float*)d_in[10];
    const float* br0  = (const float*)d_in[11];
    const float* att0 = (const float*)d_in[12];
    const float* bo0  = (const float*)d_in[13];
    const float* Wl1  = (const float*)d_in[14];
    const float* bl1  = (const float*)d_in[15];
    const float* Wr1  = (const float*)d_in[16];
    const float* br1  = (const float*)d_in[17];
    const float* att1 = (const float*)d_in[18];
    const float* bo1  = (const float*)d_in[19];
    const float* W2   = (const float*)d_in[20];
    const float* b2   = (const float*)d_in[21];
    const float* g2   = (const float*)d_in[22];
    const float* be2  = (const float*)d_in[23];
    const float* m2   = (const float*)d_in[24];
    const float* v2   = (const float*)d_in[25];
    float* out = (float*)d_out;

    float *H, *H2, *XL, *XR, *P;
    cudaGetSymbolAddress((void**)&H,  g_H);
    cudaGetSymbolAddress((void**)&H2, g_H2);
    cudaGetSymbolAddress((void**)&XL, g_XL);
    cudaGetSymbolAddress((void**)&XR, g_XR);
    cudaGetSymbolAddress((void**)&P,  g_pool);

    cudaFuncSetAttribute(gat_kernel, cudaFuncAttributeMaxDynamicSharedMemorySize, GAT_SMEM);

    const int M = BB * NN;  // 16384

    // edge CSR (deterministic stable sort)
    sort_edges_kernel<<<1, 256>>>(ei, ei + EE);

    // node_proj: H = gelu(bn(X @ W1 + b1))
    gemm_kernel<1><<<dim3(M / 128, HIDD / 64), 256>>>(x, W1, b1, g1, be1, m1, v1, H, M, HIDD, FIN);

    // layer 0
    gemm_kernel<0><<<dim3(M / 128, HIDD / 64), 256>>>(H, Wl0, bl0, 0, 0, 0, 0, XL, M, HIDD, HIDD);
    gemm_kernel<0><<<dim3(M / 128, HIDD / 64), 256>>>(H, Wr0, br0, 0, 0, 0, 0, XR, M, HIDD, HIDD);
    gat_kernel<<<dim3(BB, HH), 256, GAT_SMEM>>>(XL, XR, att0, bo0, H2);

    // layer 1
    gemm_kernel<0><<<dim3(M / 128, HIDD / 64), 256>>>(H2, Wl1, bl1, 0, 0, 0, 0, XL, M, HIDD, HIDD);
    gemm_kernel<0><<<dim3(M / 128, HIDD / 64), 256>>>(H2, Wr1, br1, 0, 0, 0, 0, XR, M, HIDD, HIDD);
    gat_kernel<<<dim3(BB, HH), 256, GAT_SMEM>>>(XL, XR, att1, bo1, H);

    // pool + output proj
    pool_kernel<<<BB, HIDD>>>(H, P);
    gemm2_kernel<<<BB, HIDD>>>(P, W2, b2, g2, be2, m2, v2, out);
}

// round 2
// speedup vs baseline: 1.5068x; 1.5068x over previous
#include <cuda_runtime.h>
#include <math.h>

#define BB   64
#define NN   256
#define HIDD 256
#define HH   4
#define CC   64
#define EE   8192
#define FIN  768
#define PAD  68   // floats per cached xl row (272B, 16B aligned)

// ---------------- scratch (no allocations allowed) ----------------
__device__ float g_H [(size_t)BB * NN * HIDD];
__device__ float g_H2[(size_t)BB * NN * HIDD];
__device__ float g_XL[(size_t)BB * NN * HIDD];
__device__ float g_XR[(size_t)BB * NN * HIDD];
__device__ float g_pool[BB * HIDD];
__device__ int   g_srcs[EE];
__device__ int   g_off[NN + 1];

__device__ __forceinline__ float gelu_f(float x) {
    return 0.5f * x * (1.0f + erff(x * 0.70710678118654752f));
}

// ---------------- deterministic stable counting sort of edges by dst ----------------
// single block, 256 threads; thread t owns dst value t
__global__ void sort_edges_kernel(const int* __restrict__ src, const int* __restrict__ dst) {
    __shared__ int sd[EE];          // 32 KB
    __shared__ int wsum[8];
    int t = threadIdx.x;
    for (int e = t; e < EE; e += 256) sd[e] = dst[e];
    __syncthreads();

    const int4* sd4 = (const int4*)sd;
    int c = 0;
    #pragma unroll 8
    for (int i = 0; i < EE / 4; i++) {
        int4 v = sd4[i];
        c += (v.x == t) + (v.y == t) + (v.z == t) + (v.w == t);
    }
    // exclusive prefix over 256 threads
    int lane = t & 31, w = t >> 5;
    int inc = c;
    #pragma unroll
    for (int o = 1; o < 32; o <<= 1) {
        int n = __shfl_up_sync(0xffffffffu, inc, o);
        if (lane >= o) inc += n;
    }
    if (lane == 31) wsum[w] = inc;
    __syncthreads();
    if (t == 0) {
        int run = 0;
        #pragma unroll
        for (int i = 0; i < 8; i++) { int v = wsum[i]; wsum[i] = run; run += v; }
    }
    __syncthreads();
    int myend = inc + wsum[w];
    int mystart = myend - c;

    int pos = mystart;
    for (int i = 0; i < EE / 4; i++) {
        int4 v = sd4[i];
        if (v.x == t) g_srcs[pos++] = src[4 * i + 0];
        if (v.y == t) g_srcs[pos++] = src[4 * i + 1];
        if (v.z == t) g_srcs[pos++] = src[4 * i + 2];
        if (v.w == t) g_srcs[pos++] = src[4 * i + 3];
    }
    g_off[t] = mystart;
    if (t == NN - 1) g_off[NN] = myend;
}

// ---------------- 128x128x16 double-buffered fp32 GEMM ----------------
// MODE 0: out = acc + bias
// MODE 1: out = gelu(bn(acc + bias))
template <int MODE>
__global__ void __launch_bounds__(256, 2)
gemm_kernel(const float* __restrict__ A, const float* __restrict__ Bm,
            const float* __restrict__ bias,
            const float* __restrict__ gam, const float* __restrict__ bet,
            const float* __restrict__ rm, const float* __restrict__ rv,
            float* __restrict__ C, int M, int Nn, int K) {
    __shared__ float As[2][16][128];
    __shared__ float Bs[2][16][128];

    const int tid = threadIdx.x;
    const int bm = blockIdx.x * 128;
    const int bn = blockIdx.y * 128;
    const int tx = tid & 15;   // 8 cols each
    const int ty = tid >> 4;   // 8 rows each

    // A tile: 128 rows x 16 cols = 512 float4 -> 2 per thread
    const int ar0 = tid >> 2,          ac0 = (tid & 3) << 2;
    const int ar1 = (tid + 256) >> 2,  ac1 = ac0;
    // B tile: 16 rows x 128 cols = 512 float4 -> 2 per thread
    const int br0 = tid >> 5,          bc0 = (tid & 31) << 2;
    const int br1 = (tid + 256) >> 5;

    const float* Ap0 = A + (size_t)(bm + ar0) * K + ac0;
    const float* Ap1 = A + (size_t)(bm + ar1) * K + ac1;
    const float* Bp0 = Bm + (size_t)br0 * Nn + bn + bc0;
    const float* Bp1 = Bm + (size_t)br1 * Nn + bn + bc0;

    float acc[8][8];
    #pragma unroll
    for (int i = 0; i < 8; i++)
        #pragma unroll
        for (int j = 0; j < 8; j++) acc[i][j] = 0.f;

    // prologue: stage 0
    float4 pa0 = *(const float4*)Ap0;
    float4 pa1 = *(const float4*)Ap1;
    float4 pb0 = *(const float4*)Bp0;
    float4 pb1 = *(const float4*)Bp1;
    As[0][ac0 + 0][ar0] = pa0.x; As[0][ac0 + 1][ar0] = pa0.y;
    As[0][ac0 + 2][ar0] = pa0.z; As[0][ac0 + 3][ar0] = pa0.w;
    As[0][ac1 + 0][ar1] = pa1.x; As[0][ac1 + 1][ar1] = pa1.y;
    As[0][ac1 + 2][ar1] = pa1.z; As[0][ac1 + 3][ar1] = pa1.w;
    *(float4*)&Bs[0][br0][bc0] = pb0;
    *(float4*)&Bs[0][br1][bc0] = pb1;
    __syncthreads();

    const int nsteps = K >> 4;
    int cur = 0;
    for (int kt = 0; kt < nsteps; kt++) {
        if (kt + 1 < nsteps) {
            pa0 = *(const float4*)(Ap0 + (kt + 1) * 16);
            pa1 = *(const float4*)(Ap1 + (kt + 1) * 16);
            pb0 = *(const float4*)(Bp0 + (size_t)(kt + 1) * 16 * Nn);
            pb1 = *(const float4*)(Bp1 + (size_t)(kt + 1) * 16 * Nn);
        }
        #pragma unroll
        for (int kk = 0; kk < 16; kk++) {
            float4 x0 = *(const float4*)&As[cur][kk][ty * 8 + 0];
            float4 x1 = *(const float4*)&As[cur][kk][ty * 8 + 4];
            float4 y0 = *(const float4*)&Bs[cur][kk][tx * 8 + 0];
            float4 y1 = *(const float4*)&Bs[cur][kk][tx * 8 + 4];
            float a_[8] = {x0.x, x0.y, x0.z, x0.w, x1.x, x1.y, x1.z, x1.w};
            float b_[8] = {y0.x, y0.y, y0.z, y0.w, y1.x, y1.y, y1.z, y1.w};
            #pragma unroll
            for (int i = 0; i < 8; i++)
                #pragma unroll
                for (int j = 0; j < 8; j++)
                    acc[i][j] = fmaf(a_[i], b_[j], acc[i][j]);
        }
        if (kt + 1 < nsteps) {
            int nxt = cur ^ 1;
            As[nxt][ac0 + 0][ar0] = pa0.x; As[nxt][ac0 + 1][ar0] = pa0.y;
            As[nxt][ac0 + 2][ar0] = pa0.z; As[nxt][ac0 + 3][ar0] = pa0.w;
            As[nxt][ac1 + 0][ar1] = pa1.x; As[nxt][ac1 + 1][ar1] = pa1.y;
            As[nxt][ac1 + 2][ar1] = pa1.z; As[nxt][ac1 + 3][ar1] = pa1.w;
            *(float4*)&Bs[nxt][br0][bc0] = pb0;
            *(float4*)&Bs[nxt][br1][bc0] = pb1;
            __syncthreads();
            cur = nxt;
        }
    }

    // epilogue
    const int col0 = bn + tx * 8;
    float bia[8], ga[8], be_[8], mm[8], vv[8];
    #pragma unroll
    for (int j = 0; j < 8; j++) bia[j] = bias[col0 + j];
    if (MODE == 1) {
        #pragma unroll
        for (int j = 0; j < 8; j++) {
            ga[j] = gam[col0 + j];
            be_[j] = bet[col0 + j];
            mm[j] = rm[col0 + j];
            vv[j] = rsqrtf(rv[col0 + j] + 1e-5f);
        }
    }
    #pragma unroll
    for (int i = 0; i < 8; i++) {
        int row = bm + ty * 8 + i;
        float t[8];
        #pragma unroll
        for (int j = 0; j < 8; j++) {
            t[j] = acc[i][j] + bia[j];
            if (MODE == 1) {
                t[j] = (t[j] - mm[j]) * vv[j] * ga[j] + be_[j];
                t[j] = gelu_f(t[j]);
            }
        }
        float4 o0 = {t[0], t[1], t[2], t[3]};
        float4 o1 = {t[4], t[5], t[6], t[7]};
        *(float4*)(C + (size_t)row * Nn + col0 + 0) = o0;
        *(float4*)(C + (size_t)row * Nn + col0 + 4) = o1;
    }
}

// ---------------- GATv2: block per (sample, head), warp per dst node ----------------
// smem: sxl[NN][PAD] + slog[EE] + satt[64] + swr[8][PAD]   ~= 102.4 KB -> 2 CTA/SM
__global__ void __launch_bounds__(256, 2)
gat_kernel(const float* __restrict__ XL, const float* __restrict__ XR,
           const float* __restrict__ att, const float* __restrict__ bo,
           float* __restrict__ OUT) {
    extern __shared__ float sm[];
    float* sxl  = sm;                     // NN*PAD
    float* slog = sxl + NN * PAD;         // EE
    float* satt = slog + EE;              // 64
    float* swr  = satt + CC;              // 8 * PAD

    const int b = blockIdx.x, h = blockIdx.y;
    const int tid = threadIdx.x;
    const int w = tid >> 5, lane = tid & 31;

    if (tid < CC) satt[tid] = att[h * CC + tid];
    const float* xlb = XL + (size_t)b * NN * HIDD + h * CC;
    for (int i = tid; i < NN * CC; i += 256) {
        int n = i >> 6, c = i & 63;
        sxl[n * PAD + c] = xlb[(size_t)n * HIDD + c];
    }
    __syncthreads();

    const float bo0 = bo[h * CC + lane];
    const float bo1 = bo[h * CC + lane + 32];
    float* swr_w = swr + w * PAD;
    const float4* at4 = (const float4*)satt;

    for (int d = w; d < NN; d += 8) {
        // xr row of this dst into per-warp scratch
        const float* xrb = XR + ((size_t)b * NN + d) * HIDD + h * CC;
        __syncwarp();
        swr_w[lane]      = xrb[lane];
        swr_w[lane + 32] = xrb[lane + 32];
        __syncwarp();

        const int e0 = g_off[d], e1 = g_off[d + 1];

        // pass 1: logits, lane-per-edge
        float mx = -3.402823466e38f;
        for (int e = e0 + lane; e < e1; e += 32) {
            int s = g_srcs[e];
            const float4* xl4 = (const float4*)(sxl + s * PAD);
            const float4* xr4 = (const float4*)swr_w;
            float acc = 0.f;
            #pragma unroll
            for (int q = 0; q < 16; q++) {
                float4 a_ = xl4[q];
                float4 r_ = xr4[q];
                float4 t4 = at4[q];
                float t;
                t = a_.x + r_.x; t = fmaxf(t, 0.2f * t); acc = fmaf(t4.x, t, acc);
                t = a_.y + r_.y; t = fmaxf(t, 0.2f * t); acc = fmaf(t4.y, t, acc);
                t = a_.z + r_.z; t = fmaxf(t, 0.2f * t); acc = fmaf(t4.z, t, acc);
                t = a_.w + r_.w; t = fmaxf(t, 0.2f * t); acc = fmaf(t4.w, t, acc);
            }
            slog[e] = acc;
            mx = fmaxf(mx, acc);
        }
        #pragma unroll
        for (int o = 16; o > 0; o >>= 1) mx = fmaxf(mx, __shfl_xor_sync(0xffffffffu, mx, o));

        // pass 2: exp + denominator
        float sum = 0.f;
        for (int e = e0 + lane; e < e1; e += 32) {
            float a = __expf(slog[e] - mx);
            slog[e] = a;
            sum += a;
        }
        #pragma unroll
        for (int o = 16; o > 0; o >>= 1) sum += __shfl_xor_sync(0xffffffffu, sum, o);
        const float inv = 1.f / (sum + 1e-16f);

        // pass 3: aggregation, lane owns channels (lane, lane+32)
        float a0 = 0.f, a1 = 0.f;
        for (int base = e0; base < e1; base += 32) {
            int ee = base + lane;
            int   sl = (ee < e1) ? g_srcs[ee] : 0;
            float wl = (ee < e1) ? slog[ee] * inv : 0.f;
            int m = min(32, e1 - base);
            for (int j = 0; j < m; j++) {
                int s   = __shfl_sync(0xffffffffu, sl, j);
                float v = __shfl_sync(0xffffffffu, wl, j);
                a0 = fmaf(v, sxl[s * PAD + lane], a0);
                a1 = fmaf(v, sxl[s * PAD + lane + 32], a1);
            }
        }
        size_t o = ((size_t)b * NN + d) * HIDD + h * CC;
        OUT[o + lane]      = gelu_f(a0 + bo0);
        OUT[o + lane + 32] = gelu_f(a1 + bo1);
    }
}

// ---------------- mean-pool over nodes ----------------
__global__ void pool_kernel(const float* __restrict__ H, float* __restrict__ P) {
    int b = blockIdx.x, f = threadIdx.x;
    float s = 0.f;
    #pragma unroll 4
    for (int n = 0; n < NN; n++) s += H[((size_t)b * NN + n) * HIDD + f];
    P[b * HIDD + f] = s * (1.0f / NN);
}

// ---------------- tiny output GEMM + BN + GELU ----------------
__global__ void gemm2_kernel(const float* __restrict__ P, const float* __restrict__ W,
                             const float* __restrict__ bias,
                             const float* __restrict__ gam, const float* __restrict__ bet,
                             const float* __restrict__ rm, const float* __restrict__ rv,
                             float* __restrict__ out) {
    __shared__ float sp[HIDD];
    int b = blockIdx.x, j = threadIdx.x;
    sp[j] = P[b * HIDD + j];
    __syncthreads();
    float acc = 0.f;
    #pragma unroll 4
    for (int k = 0; k < HIDD; k++) acc = fmaf(sp[k], W[(size_t)k * HIDD + j], acc);
    float t = acc + bias[j];
    t = (t - rm[j]) * rsqrtf(rv[j] + 1e-5f) * gam[j] + bet[j];
    out[b * HIDD + j] = gelu_f(t);
}

#define GAT_SMEM ((NN * PAD + EE + CC + 8 * PAD) * (int)sizeof(float))

extern "C" void kernel_launch(void* const* d_in, const int* in_sizes, int n_in,
                              void* d_out, int out_size) {
    const float* x    = (const float*)d_in[0];
    const int*   ei   = (const int*)d_in[1];
    const float* W1   = (const float*)d_in[2];
    const float* b1   = (const float*)d_in[3];
    const float* g1   = (const float*)d_in[4];
    const float* be1  = (const float*)d_in[5];
    const float* m1   = (const float*)d_in[6];
    const float* v1   = (const float*)d_in[7];
    const float* Wl0  = (const float*)d_in[8];
    const float* bl0  = (const float*)d_in[9];
    const float* Wr0  = (const float*)d_in[10];
    const float* br0  = (const float*)d_in[11];
    const float* att0 = (const float*)d_in[12];
    const float* bo0  = (const float*)d_in[13];
    const float* Wl1  = (const float*)d_in[14];
    const float* bl1  = (const float*)d_in[15];
    const float* Wr1  = (const float*)d_in[16];
    const float* br1  = (const float*)d_in[17];
    const float* att1 = (const float*)d_in[18];
    const float* bo1  = (const float*)d_in[19];
    const float* W2   = (const float*)d_in[20];
    const float* b2   = (const float*)d_in[21];
    const float* g2   = (const float*)d_in[22];
    const float* be2  = (const float*)d_in[23];
    const float* m2   = (const float*)d_in[24];
    const float* v2   = (const float*)d_in[25];
    float* out = (float*)d_out;

    float *H, *H2, *XL, *XR, *P;
    cudaGetSymbolAddress((void**)&H,  g_H);
    cudaGetSymbolAddress((void**)&H2, g_H2);
    cudaGetSymbolAddress((void**)&XL, g_XL);
    cudaGetSymbolAddress((void**)&XR, g_XR);
    cudaGetSymbolAddress((void**)&P,  g_pool);

    cudaFuncSetAttribute(gat_kernel, cudaFuncAttributeMaxDynamicSharedMemorySize, GAT_SMEM);

    const int M = BB * NN;  // 16384

    sort_edges_kernel<<<1, 256>>>(ei, ei + EE);

    // node_proj
    gemm_kernel<1><<<dim3(M / 128, HIDD / 128), 256>>>(x, W1, b1, g1, be1, m1, v1, H, M, HIDD, FIN);

    // layer 0
    gemm_kernel<0><<<dim3(M / 128, HIDD / 128), 256>>>(H, Wl0, bl0, 0, 0, 0, 0, XL, M, HIDD, HIDD);
    gemm_kernel<0><<<dim3(M / 128, HIDD / 128), 256>>>(H, Wr0, br0, 0, 0, 0, 0, XR, M, HIDD, HIDD);
    gat_kernel<<<dim3(BB, HH), 256, GAT_SMEM>>>(XL, XR, att0, bo0, H2);

    // layer 1
    gemm_kernel<0><<<dim3(M / 128, HIDD / 128), 256>>>(H2, Wl1, bl1, 0, 0, 0, 0, XL, M, HIDD, HIDD);
    gemm_kernel<0><<<dim3(M / 128, HIDD / 128), 256>>>(H2, Wr1, br1, 0, 0, 0, 0, XR, M, HIDD, HIDD);
    gat_kernel<<<dim3(BB, HH), 256, GAT_SMEM>>>(XL, XR, att1, bo1, H);

    // pool + output proj
    pool_kernel<<<BB, HIDD>>>(H, P);
    gemm2_kernel<<<BB, HIDD>>>(P, W2, b2, g2, be2, m2, v2, out);
}

// round 3
// speedup vs baseline: 2.0325x; 1.3489x over previous
#include <cuda_runtime.h>
#include <math.h>

#define BB   64
#define NN   256
#define HIDD 256
#define HH   4
#define CC   64
#define EE   8192
#define FIN  768
#define PAD  68   // floats per cached xl row (272B, 16B aligned)

// ---------------- scratch (no allocations allowed) ----------------
__device__ float g_H [(size_t)BB * NN * HIDD];
__device__ float g_H2[(size_t)BB * NN * HIDD];
__device__ float g_XL[(size_t)BB * NN * HIDD];
__device__ float g_XR[(size_t)BB * NN * HIDD];
__device__ float g_pool[BB * HIDD];
__device__ int   g_srcs[EE];
__device__ int   g_off[NN + 1];

__device__ __forceinline__ float gelu_f(float x) {
    return 0.5f * x * (1.0f + erff(x * 0.70710678118654752f));
}

__device__ __forceinline__ unsigned f2t(float x) {
    unsigned u;
    asm("cvt.rna.tf32.f32 %0, %1;" : "=r"(u) : "f"(x));
    return u;
}

__device__ __forceinline__ void mma8(float& c0, float& c1, float& c2, float& c3,
                                     unsigned a0, unsigned a1, unsigned a2, unsigned a3,
                                     unsigned b0, unsigned b1) {
    asm volatile(
        "mma.sync.aligned.m16n8k8.row.col.f32.tf32.tf32.f32 "
        "{%0,%1,%2,%3},{%4,%5,%6,%7},{%8,%9},{%0,%1,%2,%3};"
        : "+f"(c0), "+f"(c1), "+f"(c2), "+f"(c3)
        : "r"(a0), "r"(a1), "r"(a2), "r"(a3), "r"(b0), "r"(b1));
}

// ---------------- deterministic stable counting sort of edges by dst ----------------
__global__ void sort_edges_kernel(const int* __restrict__ src, const int* __restrict__ dst) {
    __shared__ int sd[EE];          // 32 KB
    __shared__ int wsum[8];
    int t = threadIdx.x;
    for (int e = t; e < EE; e += 256) sd[e] = dst[e];
    __syncthreads();

    const int4* sd4 = (const int4*)sd;
    int c = 0;
    #pragma unroll 8
    for (int i = 0; i < EE / 4; i++) {
        int4 v = sd4[i];
        c += (v.x == t) + (v.y == t) + (v.z == t) + (v.w == t);
    }
    int lane = t & 31, w = t >> 5;
    int inc = c;
    #pragma unroll
    for (int o = 1; o < 32; o <<= 1) {
        int n = __shfl_up_sync(0xffffffffu, inc, o);
        if (lane >= o) inc += n;
    }
    if (lane == 31) wsum[w] = inc;
    __syncthreads();
    if (t == 0) {
        int run = 0;
        #pragma unroll
        for (int i = 0; i < 8; i++) { int v = wsum[i]; wsum[i] = run; run += v; }
    }
    __syncthreads();
    int myend = inc + wsum[w];
    int mystart = myend - c;

    int pos = mystart;
    for (int i = 0; i < EE / 4; i++) {
        int4 v = sd4[i];
        if (v.x == t) g_srcs[pos++] = src[4 * i + 0];
        if (v.y == t) g_srcs[pos++] = src[4 * i + 1];
        if (v.z == t) g_srcs[pos++] = src[4 * i + 2];
        if (v.w == t) g_srcs[pos++] = src[4 * i + 3];
    }
    g_off[t] = mystart;
    if (t == NN - 1) g_off[NN] = myend;
}

// ---------------- tf32 tensor-core GEMM: 128x128 CTA tile, BK=16 ----------------
// MODE 0: out = acc + bias ;  MODE 1: out = gelu(bn(acc + bias))
#define ASTRIDE 20
#define BSTRIDE 136
template <int MODE>
__global__ void __launch_bounds__(256)
gemm_tc(const float* __restrict__ A, const float* __restrict__ Bm,
        const float* __restrict__ bias,
        const float* __restrict__ gam, const float* __restrict__ bet,
        const float* __restrict__ rm, const float* __restrict__ rv,
        float* __restrict__ C, int M, int Nn, int K) {
    __shared__ unsigned As[2][128 * ASTRIDE];   // [row][k], stride 20 (conflict-free frags)
    __shared__ unsigned Bs[2][16 * BSTRIDE];    // [k][col], stride 136

    const int tid = threadIdx.x;
    const int lane = tid & 31, wid = tid >> 5;
    const int gid = lane >> 2, tig = lane & 3;
    const int wm = wid & 1;   // 2 x 64 rows
    const int wn = wid >> 1;  // 4 x 32 cols
    const int bm = blockIdx.x * 128;
    const int bn = blockIdx.y * 128;

    // staging: A 128x16 = 512 f4 (2/thread), B 16x128 = 512 f4 (2/thread)
    const int ar0 = tid >> 2,         ac0 = (tid & 3) << 2;
    const int ar1 = (tid + 256) >> 2;
    const int bk0 = tid >> 5,         bc0 = (tid & 31) << 2;
    const int bk1 = (tid + 256) >> 5;

    const float* Ap0 = A + (size_t)(bm + ar0) * K + ac0;
    const float* Ap1 = A + (size_t)(bm + ar1) * K + ac0;
    const float* Bp0 = Bm + (size_t)bk0 * Nn + bn + bc0;
    const float* Bp1 = Bm + (size_t)bk1 * Nn + bn + bc0;

    float acc[4][4][4];
    #pragma unroll
    for (int i = 0; i < 4; i++)
        #pragma unroll
        for (int j = 0; j < 4; j++)
            #pragma unroll
            for (int q = 0; q < 4; q++) acc[i][j][q] = 0.f;

    float4 pa0 = *(const float4*)Ap0;
    float4 pa1 = *(const float4*)Ap1;
    float4 pb0 = *(const float4*)Bp0;
    float4 pb1 = *(const float4*)Bp1;

    // store stage 0 (convert to tf32 once here)
    {
        uint4 u;
        u.x = f2t(pa0.x); u.y = f2t(pa0.y); u.z = f2t(pa0.z); u.w = f2t(pa0.w);
        *(uint4*)&As[0][ar0 * ASTRIDE + ac0] = u;
        u.x = f2t(pa1.x); u.y = f2t(pa1.y); u.z = f2t(pa1.z); u.w = f2t(pa1.w);
        *(uint4*)&As[0][ar1 * ASTRIDE + ac0] = u;
        u.x = f2t(pb0.x); u.y = f2t(pb0.y); u.z = f2t(pb0.z); u.w = f2t(pb0.w);
        *(uint4*)&Bs[0][bk0 * BSTRIDE + bc0] = u;
        u.x = f2t(pb1.x); u.y = f2t(pb1.y); u.z = f2t(pb1.z); u.w = f2t(pb1.w);
        *(uint4*)&Bs[0][bk1 * BSTRIDE + bc0] = u;
    }
    __syncthreads();

    const int nsteps = K >> 4;
    int cur = 0;
    for (int kt = 0; kt < nsteps; kt++) {
        if (kt + 1 < nsteps) {
            pa0 = *(const float4*)(Ap0 + (kt + 1) * 16);
            pa1 = *(const float4*)(Ap1 + (kt + 1) * 16);
            pb0 = *(const float4*)(Bp0 + (size_t)(kt + 1) * 16 * Nn);
            pb1 = *(const float4*)(Bp1 + (size_t)(kt + 1) * 16 * Nn);
        }
        #pragma unroll
        for (int ks = 0; ks < 2; ks++) {
            const int k0 = ks * 8 + tig;
            unsigned af[4][4], bf[4][2];
            #pragma unroll
            for (int mt = 0; mt < 4; mt++) {
                int r = wm * 64 + mt * 16 + gid;
                af[mt][0] = As[cur][r * ASTRIDE + k0];
                af[mt][1] = As[cur][(r + 8) * ASTRIDE + k0];
                af[mt][2] = As[cur][r * ASTRIDE + k0 + 4];
                af[mt][3] = As[cur][(r + 8) * ASTRIDE + k0 + 4];
            }
            #pragma unroll
            for (int nt = 0; nt < 4; nt++) {
                int col = wn * 32 + nt * 8 + gid;
                bf[nt][0] = Bs[cur][k0 * BSTRIDE + col];
                bf[nt][1] = Bs[cur][(k0 + 4) * BSTRIDE + col];
            }
            #pragma unroll
            for (int mt = 0; mt < 4; mt++)
                #pragma unroll
                for (int nt = 0; nt < 4; nt++)
                    mma8(acc[mt][nt][0], acc[mt][nt][1], acc[mt][nt][2], acc[mt][nt][3],
                         af[mt][0], af[mt][1], af[mt][2], af[mt][3],
                         bf[nt][0], bf[nt][1]);
        }
        if (kt + 1 < nsteps) {
            int nxt = cur ^ 1;
            uint4 u;
            u.x = f2t(pa0.x); u.y = f2t(pa0.y); u.z = f2t(pa0.z); u.w = f2t(pa0.w);
            *(uint4*)&As[nxt][ar0 * ASTRIDE + ac0] = u;
            u.x = f2t(pa1.x); u.y = f2t(pa1.y); u.z = f2t(pa1.z); u.w = f2t(pa1.w);
            *(uint4*)&As[nxt][ar1 * ASTRIDE + ac0] = u;
            u.x = f2t(pb0.x); u.y = f2t(pb0.y); u.z = f2t(pb0.z); u.w = f2t(pb0.w);
            *(uint4*)&Bs[nxt][bk0 * BSTRIDE + bc0] = u;
            u.x = f2t(pb1.x); u.y = f2t(pb1.y); u.z = f2t(pb1.z); u.w = f2t(pb1.w);
            *(uint4*)&Bs[nxt][bk1 * BSTRIDE + bc0] = u;
            __syncthreads();
            cur = nxt;
        }
    }

    // epilogue
    #pragma unroll
    for (int nt = 0; nt < 4; nt++) {
        int col = bn + wn * 32 + nt * 8 + 2 * tig;
        float bi0 = bias[col], bi1 = bias[col + 1];
        float g0 = 1.f, g1 = 1.f, b0 = 0.f, b1 = 0.f, m0 = 0.f, m1 = 0.f, s0 = 1.f, s1 = 1.f;
        if (MODE == 1) {
            g0 = gam[col]; g1 = gam[col + 1];
            b0 = bet[col]; b1 = bet[col + 1];
            m0 = rm[col];  m1 = rm[col + 1];
            s0 = rsqrtf(rv[col] + 1e-5f);
            s1 = rsqrtf(rv[col + 1] + 1e-5f);
        }
        #pragma unroll
        for (int mt = 0; mt < 4; mt++) {
            int row0 = bm + wm * 64 + mt * 16 + gid;
            float t0 = acc[mt][nt][0] + bi0;
            float t1 = acc[mt][nt][1] + bi1;
            float t2 = acc[mt][nt][2] + bi0;
            float t3 = acc[mt][nt][3] + bi1;
            if (MODE == 1) {
                t0 = gelu_f((t0 - m0) * s0 * g0 + b0);
                t1 = gelu_f((t1 - m1) * s1 * g1 + b1);
                t2 = gelu_f((t2 - m0) * s0 * g0 + b0);
                t3 = gelu_f((t3 - m1) * s1 * g1 + b1);
            }
            float2 o0 = {t0, t1};
            float2 o1 = {t2, t3};
            *(float2*)(C + (size_t)row0 * Nn + col) = o0;
            *(float2*)(C + (size_t)(row0 + 8) * Nn + col) = o1;
        }
    }
}

// ---------------- GATv2: block per (sample, head), warp per dst node ----------------
__global__ void __launch_bounds__(256, 2)
gat_kernel(const float* __restrict__ XL, const float* __restrict__ XR,
           const float* __restrict__ att, const float* __restrict__ bo,
           float* __restrict__ OUT) {
    extern __shared__ float sm[];
    float* sxl  = sm;                     // NN*PAD
    float* slog = sxl + NN * PAD;         // EE
    float* satt = slog + EE;              // 64
    float* swr  = satt + CC;              // 8 * PAD

    const int b = blockIdx.x, h = blockIdx.y;
    const int tid = threadIdx.x;
    const int w = tid >> 5, lane = tid & 31;

    if (tid < CC) satt[tid] = att[h * CC + tid];
    const float* xlb = XL + (size_t)b * NN * HIDD + h * CC;
    for (int i = tid; i < NN * CC; i += 256) {
        int n = i >> 6, c = i & 63;
        sxl[n * PAD + c] = xlb[(size_t)n * HIDD + c];
    }
    __syncthreads();

    const float bo0 = bo[h * CC + 2 * lane];
    const float bo1 = bo[h * CC + 2 * lane + 1];
    float* swr_w = swr + w * PAD;
    const float4* at4 = (const float4*)satt;
    const int* __restrict__ srcs = g_srcs;

    for (int d = w; d < NN; d += 8) {
        const float* xrb = XR + ((size_t)b * NN + d) * HIDD + h * CC;
        __syncwarp();
        float2 xr2 = {xrb[2 * lane], xrb[2 * lane + 1]};
        *(float2*)(swr_w + 2 * lane) = xr2;
        __syncwarp();

        const int e0 = g_off[d], e1 = g_off[d + 1];

        // pass 1: logits, lane-per-edge
        float mx = -3.402823466e38f;
        for (int e = e0 + lane; e < e1; e += 32) {
            int s = srcs[e];
            const float4* xl4 = (const float4*)(sxl + s * PAD);
            const float4* xr4 = (const float4*)swr_w;
            float acc = 0.f;
            #pragma unroll
            for (int q = 0; q < 16; q++) {
                float4 a_ = xl4[q];
                float4 r_ = xr4[q];
                float4 t4 = at4[q];
                float t;
                t = a_.x + r_.x; t = fmaxf(t, 0.2f * t); acc = fmaf(t4.x, t, acc);
                t = a_.y + r_.y; t = fmaxf(t, 0.2f * t); acc = fmaf(t4.y, t, acc);
                t = a_.z + r_.z; t = fmaxf(t, 0.2f * t); acc = fmaf(t4.z, t, acc);
                t = a_.w + r_.w; t = fmaxf(t, 0.2f * t); acc = fmaf(t4.w, t, acc);
            }
            slog[e] = acc;
            mx = fmaxf(mx, acc);
        }
        #pragma unroll
        for (int o = 16; o > 0; o >>= 1) mx = fmaxf(mx, __shfl_xor_sync(0xffffffffu, mx, o));

        // pass 2: exp + denominator
        float sum = 0.f;
        for (int e = e0 + lane; e < e1; e += 32) {
            float a = __expf(slog[e] - mx);
            slog[e] = a;
            sum += a;
        }
        #pragma unroll
        for (int o = 16; o > 0; o >>= 1) sum += __shfl_xor_sync(0xffffffffu, sum, o);
        const float inv = 1.f / (sum + 1e-16f);
        __syncwarp();

        // pass 3: uniform (src, weight) per edge, lane owns channels (2*lane, 2*lane+1)
        float a0 = 0.f, a1 = 0.f;
        #pragma unroll 4
        for (int e = e0; e < e1; e++) {
            int s = srcs[e];                 // warp-uniform LDG (L1)
            float wi = slog[e] * inv;        // broadcast LDS
            float2 v = *(const float2*)(sxl + s * PAD + 2 * lane);
            a0 = fmaf(wi, v.x, a0);
            a1 = fmaf(wi, v.y, a1);
        }
        size_t o = ((size_t)b * NN + d) * HIDD + h * CC + 2 * lane;
        float2 ov = {gelu_f(a0 + bo0), gelu_f(a1 + bo1)};
        *(float2*)(OUT + o) = ov;
    }
}

// ---------------- mean-pool over nodes ----------------
__global__ void pool_kernel(const float* __restrict__ H, float* __restrict__ P) {
    int b = blockIdx.x, f = threadIdx.x;
    float s = 0.f;
    #pragma unroll 4
    for (int n = 0; n < NN; n++) s += H[((size_t)b * NN + n) * HIDD + f];
    P[b * HIDD + f] = s * (1.0f / NN);
}

// ---------------- tiny output GEMM + BN + GELU ----------------
__global__ void gemm2_kernel(const float* __restrict__ P, const float* __restrict__ W,
                             const float* __restrict__ bias,
                             const float* __restrict__ gam, const float* __restrict__ bet,
                             const float* __restrict__ rm, const float* __restrict__ rv,
                             float* __restrict__ out) {
    __shared__ float sp[HIDD];
    int b = blockIdx.x, j = threadIdx.x;
    sp[j] = P[b * HIDD + j];
    __syncthreads();
    float acc = 0.f;
    #pragma unroll 4
    for (int k = 0; k < HIDD; k++) acc = fmaf(sp[k], W[(size_t)k * HIDD + j], acc);
    float t = acc + bias[j];
    t = (t - rm[j]) * rsqrtf(rv[j] + 1e-5f) * gam[j] + bet[j];
    out[b * HIDD + j] = gelu_f(t);
}

#define GAT_SMEM ((NN * PAD + EE + CC + 8 * PAD) * (int)sizeof(float))

extern "C" void kernel_launch(void* const* d_in, const int* in_sizes, int n_in,
                              void* d_out, int out_size) {
    const float* x    = (const float*)d_in[0];
    const int*   ei   = (const int*)d_in[1];
    const float* W1   = (const float*)d_in[2];
    const float* b1   = (const float*)d_in[3];
    const float* g1   = (const float*)d_in[4];
    const float* be1  = (const float*)d_in[5];
    const float* m1   = (const float*)d_in[6];
    const float* v1   = (const float*)d_in[7];
    const float* Wl0  = (const float*)d_in[8];
    const float* bl0  = (const float*)d_in[9];
    const float* Wr0  = (const float*)d_in[10];
    const float* br0  = (const float*)d_in[11];
    const float* att0 = (const float*)d_in[12];
    const float* bo0  = (const float*)d_in[13];
    const float* Wl1  = (const float*)d_in[14];
    const float* bl1  = (const float*)d_in[15];
    const float* Wr1  = (const float*)d_in[16];
    const float* br1  = (const float*)d_in[17];
    const float* att1 = (const float*)d_in[18];
    const float* bo1  = (const float*)d_in[19];
    const float* W2   = (const float*)d_in[20];
    const float* b2   = (const float*)d_in[21];
    const float* g2   = (const float*)d_in[22];
    const float* be2  = (const float*)d_in[23];
    const float* m2   = (const float*)d_in[24];
    const float* v2   = (const float*)d_in[25];
    float* out = (float*)d_out;

    float *H, *H2, *XL, *XR, *P;
    cudaGetSymbolAddress((void**)&H,  g_H);
    cudaGetSymbolAddress((void**)&H2, g_H2);
    cudaGetSymbolAddress((void**)&XL, g_XL);
    cudaGetSymbolAddress((void**)&XR, g_XR);
    cudaGetSymbolAddress((void**)&P,  g_pool);

    cudaFuncSetAttribute(gat_kernel, cudaFuncAttributeMaxDynamicSharedMemorySize, GAT_SMEM);

    const int M = BB * NN;  // 16384

    sort_edges_kernel<<<1, 256>>>(ei, ei + EE);

    // node_proj
    gemm_tc<1><<<dim3(M / 128, HIDD / 128), 256>>>(x, W1, b1, g1, be1, m1, v1, H, M, HIDD, FIN);

    // layer 0
    gemm_tc<0><<<dim3(M / 128, HIDD / 128), 256>>>(H, Wl0, bl0, 0, 0, 0, 0, XL, M, HIDD, HIDD);
    gemm_tc<0><<<dim3(M / 128, HIDD / 128), 256>>>(H, Wr0, br0, 0, 0, 0, 0, XR, M, HIDD, HIDD);
    gat_kernel<<<dim3(BB, HH), 256, GAT_SMEM>>>(XL, XR, att0, bo0, H2);

    // layer 1
    gemm_tc<0><<<dim3(M / 128, HIDD / 128), 256>>>(H2, Wl1, bl1, 0, 0, 0, 0, XL, M, HIDD, HIDD);
    gemm_tc<0><<<dim3(M / 128, HIDD / 128), 256>>>(H2, Wr1, br1, 0, 0, 0, 0, XR, M, HIDD, HIDD);
    gat_kernel<<<dim3(BB, HH), 256, GAT_SMEM>>>(XL, XR, att1, bo1, H);

    // pool + output proj
    pool_kernel<<<BB, HIDD>>>(H, P);
    gemm2_kernel<<<BB, HIDD>>>(P, W2, b2, g2, be2, m2, v2, out);
}

// round 4
// speedup vs baseline: 2.9886x; 1.4704x over previous
#include <cuda_runtime.h>
#include <math.h>

#define BB   64
#define NN   256
#define HIDD 256
#define HH   4
#define CC   64
#define EE   8192
#define FIN  768
#define PAD  68   // floats per cached xl row (272B, 16B aligned)
#define CHUNKS 32
#define CHSZ   256   // EE / CHUNKS

// ---------------- scratch (no allocations allowed) ----------------
__device__ float g_H [(size_t)BB * NN * HIDD];
__device__ float g_H2[(size_t)BB * NN * HIDD];
__device__ float g_XL[(size_t)BB * NN * HIDD];
__device__ float g_XR[(size_t)BB * NN * HIDD];
__device__ float g_pool[BB * HIDD];
__device__ int   g_srcs[EE];
__device__ int   g_off[NN + 1];
__device__ int   g_cnt [CHUNKS][NN];
__device__ int   g_base[CHUNKS][NN];
__device__ int   g_rank[EE];

__device__ __forceinline__ float gelu_f(float x) {
    return 0.5f * x * (1.0f + erff(x * 0.70710678118654752f));
}

__device__ __forceinline__ unsigned f2t(float x) {
    unsigned u;
    asm("cvt.rna.tf32.f32 %0, %1;" : "=r"(u) : "f"(x));
    return u;
}

__device__ __forceinline__ void mma8(float& c0, float& c1, float& c2, float& c3,
                                     unsigned a0, unsigned a1, unsigned a2, unsigned a3,
                                     unsigned b0, unsigned b1) {
    asm volatile(
        "mma.sync.aligned.m16n8k8.row.col.f32.tf32.tf32.f32 "
        "{%0,%1,%2,%3},{%4,%5,%6,%7},{%8,%9},{%0,%1,%2,%3};"
        : "+f"(c0), "+f"(c1), "+f"(c2), "+f"(c3)
        : "r"(a0), "r"(a1), "r"(a2), "r"(a3), "r"(b0), "r"(b1));
}

// ---------------- parallel deterministic counting sort, 3 phases ----------------
// Phase 1: per-chunk stable ranks + per-(chunk,dst) counts
__global__ void sort_p1(const int* __restrict__ dst) {
    __shared__ int sd[CHSZ];
    const int ch = blockIdx.x, e = threadIdx.x;
    const int d = dst[ch * CHSZ + e];
    sd[e] = d;
    g_cnt[ch][e] = 0;            // NN == CHSZ, each thread zeroes one dst slot
    __syncthreads();
    int rank = 0, tot = 0;
    #pragma unroll 8
    for (int j = 0; j < CHSZ; j++) {
        int v = sd[j];           // warp-uniform -> broadcast LDS
        int m = (v == d);
        tot += m;
        rank += m & (j < e);
    }
    g_rank[ch * CHSZ + e] = rank;
    if (rank == 0) g_cnt[ch][d] = tot;   // first occurrence writes count
}

// Phase 2: bases + CSR offsets (1 block, 256 threads; thread t owns dst t)
__global__ void sort_p2() {
    __shared__ int wsum[8];
    const int t = threadIdx.x;
    int run = 0;
    #pragma unroll
    for (int c = 0; c < CHUNKS; c++) {
        g_base[c][t] = run;
        run += g_cnt[c][t];
    }
    // exclusive prefix of per-dst totals over 256 threads
    const int lane = t & 31, w = t >> 5;
    int inc = run;
    #pragma unroll
    for (int o = 1; o < 32; o <<= 1) {
        int n = __shfl_up_sync(0xffffffffu, inc, o);
        if (lane >= o) inc += n;
    }
    if (lane == 31) wsum[w] = inc;
    __syncthreads();
    if (t == 0) {
        int r = 0;
        #pragma unroll
        for (int i = 0; i < 8; i++) { int v = wsum[i]; wsum[i] = r; r += v; }
    }
    __syncthreads();
    const int offset = inc + wsum[w] - run;   // exclusive prefix
    #pragma unroll
    for (int c = 0; c < CHUNKS; c++) g_base[c][t] += offset;
    g_off[t] = offset;
    if (t == NN - 1) g_off[NN] = EE;
}

// Phase 3: scatter
__global__ void sort_p3(const int* __restrict__ src, const int* __restrict__ dst) {
    const int e = blockIdx.x * CHSZ + threadIdx.x;
    const int d = dst[e];
    g_srcs[g_base[blockIdx.x][d] + g_rank[e]] = src[e];
}

// ---------------- tf32 tensor-core GEMM: 128x128 CTA tile, BK=16 ----------------
#define ASTRIDE 20
#define BSTRIDE 136
template <int MODE>
__global__ void __launch_bounds__(256)
gemm_tc(const float* __restrict__ A, const float* __restrict__ Bm,
        const float* __restrict__ bias,
        const float* __restrict__ gam, const float* __restrict__ bet,
        const float* __restrict__ rm, const float* __restrict__ rv,
        float* __restrict__ C, int M, int Nn, int K) {
    __shared__ unsigned As[2][128 * ASTRIDE];
    __shared__ unsigned Bs[2][16 * BSTRIDE];

    const int tid = threadIdx.x;
    const int lane = tid & 31, wid = tid >> 5;
    const int gid = lane >> 2, tig = lane & 3;
    const int wm = wid & 1;
    const int wn = wid >> 1;
    const int bm = blockIdx.x * 128;
    const int bn = blockIdx.y * 128;

    const int ar0 = tid >> 2,         ac0 = (tid & 3) << 2;
    const int ar1 = (tid + 256) >> 2;
    const int bk0 = tid >> 5,         bc0 = (tid & 31) << 2;
    const int bk1 = (tid + 256) >> 5;

    const float* Ap0 = A + (size_t)(bm + ar0) * K + ac0;
    const float* Ap1 = A + (size_t)(bm + ar1) * K + ac0;
    const float* Bp0 = Bm + (size_t)bk0 * Nn + bn + bc0;
    const float* Bp1 = Bm + (size_t)bk1 * Nn + bn + bc0;

    float acc[4][4][4];
    #pragma unroll
    for (int i = 0; i < 4; i++)
        #pragma unroll
        for (int j = 0; j < 4; j++)
            #pragma unroll
            for (int q = 0; q < 4; q++) acc[i][j][q] = 0.f;

    float4 pa0 = *(const float4*)Ap0;
    float4 pa1 = *(const float4*)Ap1;
    float4 pb0 = *(const float4*)Bp0;
    float4 pb1 = *(const float4*)Bp1;

    {
        uint4 u;
        u.x = f2t(pa0.x); u.y = f2t(pa0.y); u.z = f2t(pa0.z); u.w = f2t(pa0.w);
        *(uint4*)&As[0][ar0 * ASTRIDE + ac0] = u;
        u.x = f2t(pa1.x); u.y = f2t(pa1.y); u.z = f2t(pa1.z); u.w = f2t(pa1.w);
        *(uint4*)&As[0][ar1 * ASTRIDE + ac0] = u;
        u.x = f2t(pb0.x); u.y = f2t(pb0.y); u.z = f2t(pb0.z); u.w = f2t(pb0.w);
        *(uint4*)&Bs[0][bk0 * BSTRIDE + bc0] = u;
        u.x = f2t(pb1.x); u.y = f2t(pb1.y); u.z = f2t(pb1.z); u.w = f2t(pb1.w);
        *(uint4*)&Bs[0][bk1 * BSTRIDE + bc0] = u;
    }
    __syncthreads();

    const int nsteps = K >> 4;
    int cur = 0;
    for (int kt = 0; kt < nsteps; kt++) {
        if (kt + 1 < nsteps) {
            pa0 = *(const float4*)(Ap0 + (kt + 1) * 16);
            pa1 = *(const float4*)(Ap1 + (kt + 1) * 16);
            pb0 = *(const float4*)(Bp0 + (size_t)(kt + 1) * 16 * Nn);
            pb1 = *(const float4*)(Bp1 + (size_t)(kt + 1) * 16 * Nn);
        }
        #pragma unroll
        for (int ks = 0; ks < 2; ks++) {
            const int k0 = ks * 8 + tig;
            unsigned af[4][4], bf[4][2];
            #pragma unroll
            for (int mt = 0; mt < 4; mt++) {
                int r = wm * 64 + mt * 16 + gid;
                af[mt][0] = As[cur][r * ASTRIDE + k0];
                af[mt][1] = As[cur][(r + 8) * ASTRIDE + k0];
                af[mt][2] = As[cur][r * ASTRIDE + k0 + 4];
                af[mt][3] = As[cur][(r + 8) * ASTRIDE + k0 + 4];
            }
            #pragma unroll
            for (int nt = 0; nt < 4; nt++) {
                int col = wn * 32 + nt * 8 + gid;
                bf[nt][0] = Bs[cur][k0 * BSTRIDE + col];
                bf[nt][1] = Bs[cur][(k0 + 4) * BSTRIDE + col];
            }
            #pragma unroll
            for (int mt = 0; mt < 4; mt++)
                #pragma unroll
                for (int nt = 0; nt < 4; nt++)
                    mma8(acc[mt][nt][0], acc[mt][nt][1], acc[mt][nt][2], acc[mt][nt][3],
                         af[mt][0], af[mt][1], af[mt][2], af[mt][3],
                         bf[nt][0], bf[nt][1]);
        }
        if (kt + 1 < nsteps) {
            int nxt = cur ^ 1;
            uint4 u;
            u.x = f2t(pa0.x); u.y = f2t(pa0.y); u.z = f2t(pa0.z); u.w = f2t(pa0.w);
            *(uint4*)&As[nxt][ar0 * ASTRIDE + ac0] = u;
            u.x = f2t(pa1.x); u.y = f2t(pa1.y); u.z = f2t(pa1.z); u.w = f2t(pa1.w);
            *(uint4*)&As[nxt][ar1 * ASTRIDE + ac0] = u;
            u.x = f2t(pb0.x); u.y = f2t(pb0.y); u.z = f2t(pb0.z); u.w = f2t(pb0.w);
            *(uint4*)&Bs[nxt][bk0 * BSTRIDE + bc0] = u;
            u.x = f2t(pb1.x); u.y = f2t(pb1.y); u.z = f2t(pb1.z); u.w = f2t(pb1.w);
            *(uint4*)&Bs[nxt][bk1 * BSTRIDE + bc0] = u;
            __syncthreads();
            cur = nxt;
        }
    }

    #pragma unroll
    for (int nt = 0; nt < 4; nt++) {
        int col = bn + wn * 32 + nt * 8 + 2 * tig;
        float bi0 = bias[col], bi1 = bias[col + 1];
        float g0 = 1.f, g1 = 1.f, b0 = 0.f, b1 = 0.f, m0 = 0.f, m1 = 0.f, s0 = 1.f, s1 = 1.f;
        if (MODE == 1) {
            g0 = gam[col]; g1 = gam[col + 1];
            b0 = bet[col]; b1 = bet[col + 1];
            m0 = rm[col];  m1 = rm[col + 1];
            s0 = rsqrtf(rv[col] + 1e-5f);
            s1 = rsqrtf(rv[col + 1] + 1e-5f);
        }
        #pragma unroll
        for (int mt = 0; mt < 4; mt++) {
            int row0 = bm + wm * 64 + mt * 16 + gid;
            float t0 = acc[mt][nt][0] + bi0;
            float t1 = acc[mt][nt][1] + bi1;
            float t2 = acc[mt][nt][2] + bi0;
            float t3 = acc[mt][nt][3] + bi1;
            if (MODE == 1) {
                t0 = gelu_f((t0 - m0) * s0 * g0 + b0);
                t1 = gelu_f((t1 - m1) * s1 * g1 + b1);
                t2 = gelu_f((t2 - m0) * s0 * g0 + b0);
                t3 = gelu_f((t3 - m1) * s1 * g1 + b1);
            }
            float2 o0 = {t0, t1};
            float2 o1 = {t2, t3};
            *(float2*)(C + (size_t)row0 * Nn + col) = o0;
            *(float2*)(C + (size_t)(row0 + 8) * Nn + col) = o1;
        }
    }
}

// ---------------- GATv2: block per (sample, head), warp per dst node ----------------
__global__ void __launch_bounds__(256, 2)
gat_kernel(const float* __restrict__ XL, const float* __restrict__ XR,
           const float* __restrict__ att, const float* __restrict__ bo,
           float* __restrict__ OUT) {
    extern __shared__ float sm[];
    float* sxl  = sm;                     // NN*PAD
    float* slog = sxl + NN * PAD;         // EE
    float* satt = slog + EE;              // 64
    float* swr  = satt + CC;              // 8 * PAD

    const int b = blockIdx.x, h = blockIdx.y;
    const int tid = threadIdx.x;
    const int w = tid >> 5, lane = tid & 31;

    if (tid < CC) satt[tid] = att[h * CC + tid];
    const float* xlb = XL + (size_t)b * NN * HIDD + h * CC;
    for (int i = tid; i < NN * CC; i += 256) {
        int n = i >> 6, c = i & 63;
        sxl[n * PAD + c] = xlb[(size_t)n * HIDD + c];
    }
    __syncthreads();

    const float bo0 = bo[h * CC + 2 * lane];
    const float bo1 = bo[h * CC + 2 * lane + 1];
    float* swr_w = swr + w * PAD;
    const float4* at4 = (const float4*)satt;
    const int* __restrict__ srcs = g_srcs;

    for (int d = w; d < NN; d += 8) {
        const float* xrb = XR + ((size_t)b * NN + d) * HIDD + h * CC;
        __syncwarp();
        float2 xr2 = {xrb[2 * lane], xrb[2 * lane + 1]};
        *(float2*)(swr_w + 2 * lane) = xr2;
        __syncwarp();

        const int e0 = g_off[d], e1 = g_off[d + 1];

        float mx = -3.402823466e38f;
        for (int e = e0 + lane; e < e1; e += 32) {
            int s = srcs[e];
            const float4* xl4 = (const float4*)(sxl + s * PAD);
            const float4* xr4 = (const float4*)swr_w;
            float acc = 0.f;
            #pragma unroll
            for (int q = 0; q < 16; q++) {
                float4 a_ = xl4[q];
                float4 r_ = xr4[q];
                float4 t4 = at4[q];
                float t;
                t = a_.x + r_.x; t = fmaxf(t, 0.2f * t); acc = fmaf(t4.x, t, acc);
                t = a_.y + r_.y; t = fmaxf(t, 0.2f * t); acc = fmaf(t4.y, t, acc);
                t = a_.z + r_.z; t = fmaxf(t, 0.2f * t); acc = fmaf(t4.z, t, acc);
                t = a_.w + r_.w; t = fmaxf(t, 0.2f * t); acc = fmaf(t4.w, t, acc);
            }
            slog[e] = acc;
            mx = fmaxf(mx, acc);
        }
        #pragma unroll
        for (int o = 16; o > 0; o >>= 1) mx = fmaxf(mx, __shfl_xor_sync(0xffffffffu, mx, o));

        float sum = 0.f;
        for (int e = e0 + lane; e < e1; e += 32) {
            float a = __expf(slog[e] - mx);
            slog[e] = a;
            sum += a;
        }
        #pragma unroll
        for (int o = 16; o > 0; o >>= 1) sum += __shfl_xor_sync(0xffffffffu, sum, o);
        const float inv = 1.f / (sum + 1e-16f);
        __syncwarp();

        float a0 = 0.f, a1 = 0.f;
        #pragma unroll 4
        for (int e = e0; e < e1; e++) {
            int s = srcs[e];
            float wi = slog[e] * inv;
            float2 v = *(const float2*)(sxl + s * PAD + 2 * lane);
            a0 = fmaf(wi, v.x, a0);
            a1 = fmaf(wi, v.y, a1);
        }
        size_t o = ((size_t)b * NN + d) * HIDD + h * CC + 2 * lane;
        float2 ov = {gelu_f(a0 + bo0), gelu_f(a1 + bo1)};
        *(float2*)(OUT + o) = ov;
    }
}

// ---------------- mean-pool over nodes ----------------
__global__ void pool_kernel(const float* __restrict__ H, float* __restrict__ P) {
    int b = blockIdx.x, f = threadIdx.x;
    float s = 0.f;
    #pragma unroll 4
    for (int n = 0; n < NN; n++) s += H[((size_t)b * NN + n) * HIDD + f];
    P[b * HIDD + f] = s * (1.0f / NN);
}

// ---------------- tiny output GEMM + BN + GELU ----------------
__global__ void gemm2_kernel(const float* __restrict__ P, const float* __restrict__ W,
                             const float* __restrict__ bias,
                             const float* __restrict__ gam, const float* __restrict__ bet,
                             const float* __restrict__ rm, const float* __restrict__ rv,
                             float* __restrict__ out) {
    __shared__ float sp[HIDD];
    int b = blockIdx.x, j = threadIdx.x;
    sp[j] = P[b * HIDD + j];
    __syncthreads();
    float acc = 0.f;
    #pragma unroll 4
    for (int k = 0; k < HIDD; k++) acc = fmaf(sp[k], W[(size_t)k * HIDD + j], acc);
    float t = acc + bias[j];
    t = (t - rm[j]) * rsqrtf(rv[j] + 1e-5f) * gam[j] + bet[j];
    out[b * HIDD + j] = gelu_f(t);
}

#define GAT_SMEM ((NN * PAD + EE + CC + 8 * PAD) * (int)sizeof(float))

extern "C" void kernel_launch(void* const* d_in, const int* in_sizes, int n_in,
                              void* d_out, int out_size) {
    const float* x    = (const float*)d_in[0];
    const int*   ei   = (const int*)d_in[1];
    const float* W1   = (const float*)d_in[2];
    const float* b1   = (const float*)d_in[3];
    const float* g1   = (const float*)d_in[4];
    const float* be1  = (const float*)d_in[5];
    const float* m1   = (const float*)d_in[6];
    const float* v1   = (const float*)d_in[7];
    const float* Wl0  = (const float*)d_in[8];
    const float* bl0  = (const float*)d_in[9];
    const float* Wr0  = (const float*)d_in[10];
    const float* br0  = (const float*)d_in[11];
    const float* att0 = (const float*)d_in[12];
    const float* bo0  = (const float*)d_in[13];
    const float* Wl1  = (const float*)d_in[14];
    const float* bl1  = (const float*)d_in[15];
    const float* Wr1  = (const float*)d_in[16];
    const float* br1  = (const float*)d_in[17];
    const float* att1 = (const float*)d_in[18];
    const float* bo1  = (const float*)d_in[19];
    const float* W2   = (const float*)d_in[20];
    const float* b2   = (const float*)d_in[21];
    const float* g2   = (const float*)d_in[22];
    const float* be2  = (const float*)d_in[23];
    const float* m2   = (const float*)d_in[24];
    const float* v2   = (const float*)d_in[25];
    float* out = (float*)d_out;

    float *H, *H2, *XL, *XR, *P;
    cudaGetSymbolAddress((void**)&H,  g_H);
    cudaGetSymbolAddress((void**)&H2, g_H2);
    cudaGetSymbolAddress((void**)&XL, g_XL);
    cudaGetSymbolAddress((void**)&XR, g_XR);
    cudaGetSymbolAddress((void**)&P,  g_pool);

    cudaFuncSetAttribute(gat_kernel, cudaFuncAttributeMaxDynamicSharedMemorySize, GAT_SMEM);

    const int M = BB * NN;  // 16384
    const int* src = ei;
    const int* dst = ei + EE;

    // parallel deterministic edge sort
    sort_p1<<<CHUNKS, CHSZ>>>(dst);
    sort_p2<<<1, 256>>>();
    sort_p3<<<CHUNKS, CHSZ>>>(src, dst);

    // node_proj
    gemm_tc<1><<<dim3(M / 128, HIDD / 128), 256>>>(x, W1, b1, g1, be1, m1, v1, H, M, HIDD, FIN);

    // layer 0
    gemm_tc<0><<<dim3(M / 128, HIDD / 128), 256>>>(H, Wl0, bl0, 0, 0, 0, 0, XL, M, HIDD, HIDD);
    gemm_tc<0><<<dim3(M / 128, HIDD / 128), 256>>>(H, Wr0, br0, 0, 0, 0, 0, XR, M, HIDD, HIDD);
    gat_kernel<<<dim3(BB, HH), 256, GAT_SMEM>>>(XL, XR, att0, bo0, H2);

    // layer 1
    gemm_tc<0><<<dim3(M / 128, HIDD / 128), 256>>>(H2, Wl1, bl1, 0, 0, 0, 0, XL, M, HIDD, HIDD);
    gemm_tc<0><<<dim3(M / 128, HIDD / 128), 256>>>(H2, Wr1, br1, 0, 0, 0, 0, XR, M, HIDD, HIDD);
    gat_kernel<<<dim3(BB, HH), 256, GAT_SMEM>>>(XL, XR, att1, bo1, H);

    // pool + output proj
    pool_kernel<<<BB, HIDD>>>(H, P);
    gemm2_kernel<<<BB, HIDD>>>(P, W2, b2, g2, be2, m2, v2, out);
}